// round 10
// baseline (speedup 1.0000x reference)
#include <cuda_runtime.h>
#include <cuda_fp16.h>

// CapsuleLayer dynamic routing, GB300 (sm_103a).
// x[B=128][R=1152][Ci=8], W[C=10][R=1152][Ci=8][O=16], 3 routing iterations.
// out v: [C][B][1][1][O] = 20480 fp32.
//
// logits_t = u * A_t; per iter per (c,b,o): E=sum_r exp(u*A), S=sum_r u*exp(u*A).
// Iter 0: A=0 -> s0 = mean_r u, FUSED into the gemm (warp-reduced RED.ADD into
// g_s as u is produced); norm0_kernel computes n2[0]=sum s0^2.
// u fp16 (47.2 MB). NOTE: this ptxas only allows L2::evict_* hints on 256-bit
// accesses, so no cache hints here (plain stores/__ldg).
// final_kernel re-zeroes g_s for the next graph replay (gemm accumulates).

#define BB 128
#define RR 1152
#define CI 8
#define CC 10
#define OO 16
#define U_ELEMS (CC * BB * RR * OO)
#define S_ELEMS (CC * BB * OO)
#define LOG2E 1.4426950408889634f

__device__ __half g_u[U_ELEMS];
__device__ float  g_s[S_ELEMS];    // zero at module load; re-zeroed by final_kernel
__device__ float  g_A[S_ELEMS];
__device__ float  g_n2[4];

__device__ __forceinline__ float ex2f(float x) {
    float r;
    asm("ex2.approx.f32 %0, %1;" : "=f"(r) : "f"(x));
    return r;
}

// ---------------------------------------------------------------------------
// GEMM: u[c][b][r][o] = sum_i x[b][r][i] * W[c][r][i][o], fp16 out.
// Fused s0 partials: per b, butterfly-reduce acc over the warp's 4 r's and
// RED.ADD the 16 o-values into g_s[c][b][:]. Also zeroes g_n2.
// ---------------------------------------------------------------------------
#define RB 32
#define BT 32

__global__ __launch_bounds__(256, 4)
void gemm_kernel(const float* __restrict__ x, const float* __restrict__ W) {
    const int c     = blockIdx.y;
    const int rbase = blockIdx.x * RB;
    const int tid   = threadIdx.x;
    const int r     = tid >> 3;
    const int og    = tid & 7;
    const int o0    = og * 2;
    const int lane  = tid & 31;

    if (blockIdx.x == 0 && blockIdx.y == 0 && tid < 4) g_n2[tid] = 0.0f;

    float w0[CI], w1[CI];
    {
        const float* Wp = W + ((size_t)c * RR + rbase + r) * (CI * OO) + o0;
        #pragma unroll
        for (int i = 0; i < CI; i++) {
            w0[i] = Wp[i * OO];
            w1[i] = Wp[i * OO + 1];
        }
    }

    // RED target o for this lane (lanes 0..15 active):
    // lanes 0..7 -> o = 2*lane (carries p0); lanes 8..15 -> o = 2*(lane-8)+1 (p1).
    const int red_o = (lane < 8) ? (2 * lane) : (2 * (lane - 8) + 1);

    __shared__ float xs[BT][RB * CI];   // 32 KB

    for (int bt = 0; bt < BB; bt += BT) {
        __syncthreads();
        for (int v = tid; v < BT * RB * CI / 4; v += 256) {
            int b = v >> 6;
            int q = v & 63;
            const float4* src = (const float4*)(x + ((size_t)(bt + b) * RR + rbase) * CI);
            ((float4*)xs[b])[q] = src[q];
        }
        __syncthreads();

        #pragma unroll 4
        for (int b = 0; b < BT; b++) {
            float4 xa = *(const float4*)&xs[b][r * CI];
            float4 xb = *(const float4*)&xs[b][r * CI + 4];
            float acc0, acc1;
            acc0 = xa.x * w0[0];
            acc1 = xa.x * w1[0];
            acc0 = fmaf(xa.y, w0[1], acc0);  acc1 = fmaf(xa.y, w1[1], acc1);
            acc0 = fmaf(xa.z, w0[2], acc0);  acc1 = fmaf(xa.z, w1[2], acc1);
            acc0 = fmaf(xa.w, w0[3], acc0);  acc1 = fmaf(xa.w, w1[3], acc1);
            acc0 = fmaf(xb.x, w0[4], acc0);  acc1 = fmaf(xb.x, w1[4], acc1);
            acc0 = fmaf(xb.y, w0[5], acc0);  acc1 = fmaf(xb.y, w1[5], acc1);
            acc0 = fmaf(xb.z, w0[6], acc0);  acc1 = fmaf(xb.z, w1[6], acc1);
            acc0 = fmaf(xb.w, w0[7], acc0);  acc1 = fmaf(xb.w, w1[7], acc1);

            size_t uidx = (((size_t)c * BB + bt + b) * RR + rbase + r) * OO + o0;
            *(__half2*)&g_u[uidx] = __floats2half2_rn(acc0, acc1);

            // s0 partial: reduce over the warp's 4 r's (lane bits 3,4)
            float p0 = acc0 + __shfl_xor_sync(0xffffffffu, acc0, 8);
            p0 += __shfl_xor_sync(0xffffffffu, p0, 16);
            float p1 = acc1 + __shfl_xor_sync(0xffffffffu, acc1, 8);
            p1 += __shfl_xor_sync(0xffffffffu, p1, 16);
            if (lane < 16) {
                float val = (lane < 8) ? p0 : p1;
                atomicAdd(&g_s[((size_t)c * BB + bt + b) * OO + red_o],
                          val * (1.0f / RR));
            }
        }
    }
}

// ---------------------------------------------------------------------------
// n2[0] = sum over all 20480 of s0^2. grid 40 x 512.
// ---------------------------------------------------------------------------
__global__ __launch_bounds__(512)
void norm0_kernel() {
    const int tid = threadIdx.x;
    const int i   = blockIdx.x * 512 + tid;
    float v = g_s[i];
    float q = v * v;
    #pragma unroll
    for (int off = 16; off; off >>= 1)
        q += __shfl_xor_sync(0xffffffffu, q, off);

    __shared__ float wr[16];
    if ((tid & 31) == 0) wr[tid >> 5] = q;
    __syncthreads();
    if (tid < 16) {
        float a = wr[tid];
        #pragma unroll
        for (int off = 8; off; off >>= 1)
            a += __shfl_xor_sync(0x0000ffffu, a, off);
        if (tid == 0) atomicAdd(&g_n2[0], a);
    }
}

// ---------------------------------------------------------------------------
// Iterations t=1,2. Prologue applies previous squash; maintains g_A.
// exp(u*a) = ex2(u * (a*log2e)). 6-deep batched 64-bit __ldg loads.
// ---------------------------------------------------------------------------
__global__ __launch_bounds__(256, 5)
void iter_kernel(int t) {
    const int blk = blockIdx.x;
    const int tid = threadIdx.x;
    const int og  = tid & 3;
    const int rg  = tid >> 2;
    const __half* __restrict__ p =
        g_u + (size_t)blk * (RR * OO) + og * 4 + rg * OO;

    __shared__ float sA[16];

    if (tid < 16) {
        float n2 = g_n2[t - 1];
        float sc = sqrtf(n2) / (1.0f + n2);
        float v  = sc * g_s[blk * OO + tid];
        float a;
        if (t == 1) {
            a = v;
            g_A[blk * OO + tid] = a;   // written at t=1, read only at t=2
        } else {
            a = g_A[blk * OO + tid] + v;
        }
        sA[tid] = a * LOG2E;
    }
    __syncthreads();

    const float a0 = sA[og * 4 + 0];
    const float a1 = sA[og * 4 + 1];
    const float a2 = sA[og * 4 + 2];
    const float a3 = sA[og * 4 + 3];

    float E0 = 0.f, E1 = 0.f, E2 = 0.f, E3 = 0.f;
    float S0 = 0.f, S1 = 0.f, S2 = 0.f, S3 = 0.f;

    for (int jj = 0; jj < 3; jj++) {
        uint2 v[6];
        #pragma unroll
        for (int j = 0; j < 6; j++)
            v[j] = __ldg((const uint2*)(p + j * (64 * OO)));
        p += 6 * 64 * OO;
        #pragma unroll
        for (int j = 0; j < 6; j++) {
            float2 f0 = __half22float2(*(__half2*)&v[j].x);
            float2 f1 = __half22float2(*(__half2*)&v[j].y);
            float e0 = ex2f(f0.x * a0); E0 += e0; S0 = fmaf(e0, f0.x, S0);
            float e1 = ex2f(f0.y * a1); E1 += e1; S1 = fmaf(e1, f0.y, S1);
            float e2 = ex2f(f1.x * a2); E2 += e2; S2 = fmaf(e2, f1.x, S2);
            float e3 = ex2f(f1.y * a3); E3 += e3; S3 = fmaf(e3, f1.y, S3);
        }
    }

    #pragma unroll
    for (int off = 4; off <= 16; off <<= 1) {
        E0 += __shfl_xor_sync(0xffffffffu, E0, off);
        E1 += __shfl_xor_sync(0xffffffffu, E1, off);
        E2 += __shfl_xor_sync(0xffffffffu, E2, off);
        E3 += __shfl_xor_sync(0xffffffffu, E3, off);
        S0 += __shfl_xor_sync(0xffffffffu, S0, off);
        S1 += __shfl_xor_sync(0xffffffffu, S1, off);
        S2 += __shfl_xor_sync(0xffffffffu, S2, off);
        S3 += __shfl_xor_sync(0xffffffffu, S3, off);
    }

    __shared__ float pE[8][16], pS[8][16];
    const int warp = tid >> 5;
    const int lane = tid & 31;
    if (lane < 4) {
        *(float4*)&pE[warp][lane * 4] = make_float4(E0, E1, E2, E3);
        *(float4*)&pS[warp][lane * 4] = make_float4(S0, S1, S2, S3);
    }
    __syncthreads();

    if (tid < 16) {
        float Et = 0.0f, St = 0.0f;
        #pragma unroll
        for (int w = 0; w < 8; w++) { Et += pE[w][tid]; St += pS[w][tid]; }
        float s = St / Et;
        g_s[blk * OO + tid] = s;

        float q = s * s;
        q += __shfl_xor_sync(0x0000ffffu, q, 1);
        q += __shfl_xor_sync(0x0000ffffu, q, 2);
        q += __shfl_xor_sync(0x0000ffffu, q, 4);
        q += __shfl_xor_sync(0x0000ffffu, q, 8);
        if (tid == 0) atomicAdd(&g_n2[t], q);
    }
}

// ---------------------------------------------------------------------------
// Final: out = scale(n2[2]) * s2; zero g_s for the next graph replay
// (gemm accumulates s0 into g_s, so it must start at 0 every launch).
// ---------------------------------------------------------------------------
__global__ __launch_bounds__(256)
void final_kernel(float* __restrict__ out) {
    int i = blockIdx.x * blockDim.x + threadIdx.x;
    if (i < S_ELEMS) {
        float n2 = g_n2[2];
        float sc = sqrtf(n2) / (1.0f + n2);
        out[i] = sc * g_s[i];
        g_s[i] = 0.0f;
    }
}

// ---------------------------------------------------------------------------
extern "C" void kernel_launch(void* const* d_in, const int* in_sizes, int n_in,
                              void* d_out, int out_size) {
    const float* x = (const float*)d_in[0];   // [128][1152][8]
    const float* W = (const float*)d_in[1];   // [10][1152][8][16]
    float* out = (float*)d_out;               // [10][128][1][1][16]

    gemm_kernel<<<dim3(RR / RB, CC), 256>>>(x, W);
    norm0_kernel<<<S_ELEMS / 512, 512>>>();
    iter_kernel<<<CC * BB, 256>>>(1);
    iter_kernel<<<CC * BB, 256>>>(2);
    final_kernel<<<(S_ELEMS + 255) / 256, 256>>>(out);
}

// round 15
// speedup vs baseline: 1.4986x; 1.4986x over previous
#include <cuda_runtime.h>
#include <cuda_fp16.h>

// CapsuleLayer dynamic routing, GB300 (sm_103a).
// x[B=128][R=1152][Ci=8], W[C=10][R=1152][Ci=8][O=16], 3 routing iterations.
// out v: [C][B][1][1][O] = 20480 fp32.
//
// logits_t = u * A_t; per iter per (c,b,o): E=sum_r exp(u*A), S=sum_r u*exp(u*A).
// Iter 0: A=0 -> s0 = mean_r u (separate streaming pass; fusing it into the
// gemm was measured SLOWER). Squash: GLOBAL Frobenius norm.
// u fp16 (47.2 MB). GEMM uses packed fma.rn.f32x2 (FFMA2): halves FMA-pipe
// work; x-broadcast packs ride the ALU pipe.

#define BB 128
#define RR 1152
#define CI 8
#define CC 10
#define OO 16
#define U_ELEMS (CC * BB * RR * OO)
#define S_ELEMS (CC * BB * OO)
#define LOG2E 1.4426950408889634f

__device__ __half g_u[U_ELEMS];
__device__ float  g_s[S_ELEMS];
__device__ float  g_A[S_ELEMS];
__device__ float  g_n2[4];

__device__ __forceinline__ float ex2f(float x) {
    float r;
    asm("ex2.approx.f32 %0, %1;" : "=f"(r) : "f"(x));
    return r;
}
__device__ __forceinline__ unsigned long long pack2(float lo, float hi) {
    unsigned long long r;
    asm("mov.b64 %0, {%1, %2};" : "=l"(r) : "f"(lo), "f"(hi));
    return r;
}
__device__ __forceinline__ unsigned long long mul2(unsigned long long a,
                                                   unsigned long long b) {
    unsigned long long r;
    asm("mul.rn.f32x2 %0, %1, %2;" : "=l"(r) : "l"(a), "l"(b));
    return r;
}
__device__ __forceinline__ unsigned long long fma2(unsigned long long a,
                                                   unsigned long long b,
                                                   unsigned long long c) {
    unsigned long long r;
    asm("fma.rn.f32x2 %0, %1, %2, %3;" : "=l"(r) : "l"(a), "l"(b), "l"(c));
    return r;
}
__device__ __forceinline__ float2 unpack2(unsigned long long v) {
    float2 f;
    asm("mov.b64 {%0, %1}, %2;" : "=f"(f.x), "=f"(f.y) : "l"(v));
    return f;
}

// ---------------------------------------------------------------------------
// GEMM: u[c][b][r][o] = sum_i x[b][r][i] * W[c][r][i][o], fp16 out.
// grid (36 r-chunks, 10 c), 256 thr: (r 0..31, og 0..7) owns o0=2og,o0+1.
// W pairs packed once into 8 x f32x2; inner loop = 8 pack(ALU) + 8 FFMA2(FMA).
// Also zeroes g_n2 for graph replay.
// ---------------------------------------------------------------------------
#define RB 32
#define BT 32

__global__ __launch_bounds__(256, 4)
void gemm_kernel(const float* __restrict__ x, const float* __restrict__ W) {
    const int c     = blockIdx.y;
    const int rbase = blockIdx.x * RB;
    const int tid   = threadIdx.x;
    const int r     = tid >> 3;
    const int og    = tid & 7;
    const int o0    = og * 2;

    if (blockIdx.x == 0 && blockIdx.y == 0 && tid < 4) g_n2[tid] = 0.0f;

    unsigned long long wp[CI];
    {
        const float* Wp = W + ((size_t)c * RR + rbase + r) * (CI * OO) + o0;
        #pragma unroll
        for (int i = 0; i < CI; i++)
            wp[i] = pack2(Wp[i * OO], Wp[i * OO + 1]);
    }

    __shared__ float xs[BT][RB * CI];   // 32 KB

    for (int bt = 0; bt < BB; bt += BT) {
        __syncthreads();
        for (int v = tid; v < BT * RB * CI / 4; v += 256) {
            int b = v >> 6;
            int q = v & 63;
            const float4* src = (const float4*)(x + ((size_t)(bt + b) * RR + rbase) * CI);
            ((float4*)xs[b])[q] = src[q];
        }
        __syncthreads();

        #pragma unroll 4
        for (int b = 0; b < BT; b++) {
            float4 xa = *(const float4*)&xs[b][r * CI];
            float4 xb = *(const float4*)&xs[b][r * CI + 4];
            unsigned long long acc;
            acc = mul2(pack2(xa.x, xa.x), wp[0]);
            acc = fma2(pack2(xa.y, xa.y), wp[1], acc);
            acc = fma2(pack2(xa.z, xa.z), wp[2], acc);
            acc = fma2(pack2(xa.w, xa.w), wp[3], acc);
            acc = fma2(pack2(xb.x, xb.x), wp[4], acc);
            acc = fma2(pack2(xb.y, xb.y), wp[5], acc);
            acc = fma2(pack2(xb.z, xb.z), wp[6], acc);
            acc = fma2(pack2(xb.w, xb.w), wp[7], acc);
            float2 f = unpack2(acc);

            size_t uidx = (((size_t)c * BB + bt + b) * RR + rbase + r) * OO + o0;
            *(__half2*)&g_u[uidx] = __floats2half2_rn(f.x, f.y);
        }
    }
}

// ---------------------------------------------------------------------------
// Iteration 0 (softmax uniform): s0 = mean_r u; n2[0] += sum s0^2.
// grid 1280 (c*128+b), 256 thr = 128 rg x 2 o-halves; uint4 (8-half) loads,
// 3-deep batches in a non-unrolled 3-step outer loop.
// ---------------------------------------------------------------------------
__global__ __launch_bounds__(256, 5)
void mean_kernel() {
    const int blk = blockIdx.x;
    const int tid = threadIdx.x;
    const int og  = tid & 1;                    // o = og*8 + k
    const int rg  = tid >> 1;                   // 0..127
    const __half* __restrict__ p =
        g_u + (size_t)blk * (RR * OO) + og * 8 + rg * OO;

    float S[8];
    #pragma unroll
    for (int k = 0; k < 8; k++) S[k] = 0.0f;

    for (int jj = 0; jj < 3; jj++) {
        uint4 v[3];
        #pragma unroll
        for (int j = 0; j < 3; j++)
            v[j] = __ldg((const uint4*)(p + j * (128 * OO)));
        p += 3 * 128 * OO;
        #pragma unroll
        for (int j = 0; j < 3; j++) {
            float2 f0 = __half22float2(*(__half2*)&v[j].x);
            float2 f1 = __half22float2(*(__half2*)&v[j].y);
            float2 f2 = __half22float2(*(__half2*)&v[j].z);
            float2 f3 = __half22float2(*(__half2*)&v[j].w);
            S[0] += f0.x; S[1] += f0.y; S[2] += f1.x; S[3] += f1.y;
            S[4] += f2.x; S[5] += f2.y; S[6] += f3.x; S[7] += f3.y;
        }
    }

    #pragma unroll
    for (int off = 2; off <= 16; off <<= 1) {
        #pragma unroll
        for (int k = 0; k < 8; k++)
            S[k] += __shfl_xor_sync(0xffffffffu, S[k], off);
    }

    __shared__ float pS[8][16];
    const int warp = tid >> 5;
    const int lane = tid & 31;
    if (lane < 2) {
        #pragma unroll
        for (int k = 0; k < 8; k++) pS[warp][og * 8 + k] = S[k];
    }
    __syncthreads();

    if (tid < 16) {
        float s = 0.0f;
        #pragma unroll
        for (int w = 0; w < 8; w++) s += pS[w][tid];
        s *= (1.0f / RR);
        g_s[blk * OO + tid] = s;

        float q = s * s;
        q += __shfl_xor_sync(0x0000ffffu, q, 1);
        q += __shfl_xor_sync(0x0000ffffu, q, 2);
        q += __shfl_xor_sync(0x0000ffffu, q, 4);
        q += __shfl_xor_sync(0x0000ffffu, q, 8);
        if (tid == 0) atomicAdd(&g_n2[0], q);
    }
}

// ---------------------------------------------------------------------------
// Iterations t=1,2. Prologue applies previous squash; maintains g_A.
// exp(u*a) = ex2(u * (a*log2e)). 6-deep batched 64-bit __ldg loads.
// ---------------------------------------------------------------------------
__global__ __launch_bounds__(256, 5)
void iter_kernel(int t) {
    const int blk = blockIdx.x;
    const int tid = threadIdx.x;
    const int og  = tid & 3;
    const int rg  = tid >> 2;
    const __half* __restrict__ p =
        g_u + (size_t)blk * (RR * OO) + og * 4 + rg * OO;

    __shared__ float sA[16];

    if (tid < 16) {
        float n2 = g_n2[t - 1];
        float sc = sqrtf(n2) / (1.0f + n2);
        float v  = sc * g_s[blk * OO + tid];
        float a;
        if (t == 1) {
            a = v;
            g_A[blk * OO + tid] = a;   // written at t=1, read only at t=2
        } else {
            a = g_A[blk * OO + tid] + v;
        }
        sA[tid] = a * LOG2E;
    }
    __syncthreads();

    const float a0 = sA[og * 4 + 0];
    const float a1 = sA[og * 4 + 1];
    const float a2 = sA[og * 4 + 2];
    const float a3 = sA[og * 4 + 3];

    float E0 = 0.f, E1 = 0.f, E2 = 0.f, E3 = 0.f;
    float S0 = 0.f, S1 = 0.f, S2 = 0.f, S3 = 0.f;

    for (int jj = 0; jj < 3; jj++) {
        uint2 v[6];
        #pragma unroll
        for (int j = 0; j < 6; j++)
            v[j] = __ldg((const uint2*)(p + j * (64 * OO)));
        p += 6 * 64 * OO;
        #pragma unroll
        for (int j = 0; j < 6; j++) {
            float2 f0 = __half22float2(*(__half2*)&v[j].x);
            float2 f1 = __half22float2(*(__half2*)&v[j].y);
            float e0 = ex2f(f0.x * a0); E0 += e0; S0 = fmaf(e0, f0.x, S0);
            float e1 = ex2f(f0.y * a1); E1 += e1; S1 = fmaf(e1, f0.y, S1);
            float e2 = ex2f(f1.x * a2); E2 += e2; S2 = fmaf(e2, f1.x, S2);
            float e3 = ex2f(f1.y * a3); E3 += e3; S3 = fmaf(e3, f1.y, S3);
        }
    }

    #pragma unroll
    for (int off = 4; off <= 16; off <<= 1) {
        E0 += __shfl_xor_sync(0xffffffffu, E0, off);
        E1 += __shfl_xor_sync(0xffffffffu, E1, off);
        E2 += __shfl_xor_sync(0xffffffffu, E2, off);
        E3 += __shfl_xor_sync(0xffffffffu, E3, off);
        S0 += __shfl_xor_sync(0xffffffffu, S0, off);
        S1 += __shfl_xor_sync(0xffffffffu, S1, off);
        S2 += __shfl_xor_sync(0xffffffffu, S2, off);
        S3 += __shfl_xor_sync(0xffffffffu, S3, off);
    }

    __shared__ float pE[8][16], pS[8][16];
    const int warp = tid >> 5;
    const int lane = tid & 31;
    if (lane < 4) {
        *(float4*)&pE[warp][lane * 4] = make_float4(E0, E1, E2, E3);
        *(float4*)&pS[warp][lane * 4] = make_float4(S0, S1, S2, S3);
    }
    __syncthreads();

    if (tid < 16) {
        float Et = 0.0f, St = 0.0f;
        #pragma unroll
        for (int w = 0; w < 8; w++) { Et += pE[w][tid]; St += pS[w][tid]; }
        float s = St / Et;
        g_s[blk * OO + tid] = s;

        float q = s * s;
        q += __shfl_xor_sync(0x0000ffffu, q, 1);
        q += __shfl_xor_sync(0x0000ffffu, q, 2);
        q += __shfl_xor_sync(0x0000ffffu, q, 4);
        q += __shfl_xor_sync(0x0000ffffu, q, 8);
        if (tid == 0) atomicAdd(&g_n2[t], q);
    }
}

// ---------------------------------------------------------------------------
__global__ __launch_bounds__(256)
void final_kernel(float* __restrict__ out) {
    int i = blockIdx.x * blockDim.x + threadIdx.x;
    if (i < S_ELEMS) {
        float n2 = g_n2[2];
        float sc = sqrtf(n2) / (1.0f + n2);
        out[i] = sc * g_s[i];
    }
}

// ---------------------------------------------------------------------------
extern "C" void kernel_launch(void* const* d_in, const int* in_sizes, int n_in,
                              void* d_out, int out_size) {
    const float* x = (const float*)d_in[0];   // [128][1152][8]
    const float* W = (const float*)d_in[1];   // [10][1152][8][16]
    float* out = (float*)d_out;               // [10][128][1][1][16]

    gemm_kernel<<<dim3(RR / RB, CC), 256>>>(x, W);
    mean_kernel<<<CC * BB, 256>>>();
    iter_kernel<<<CC * BB, 256>>>(1);
    iter_kernel<<<CC * BB, 256>>>(2);
    final_kernel<<<(S_ELEMS + 255) / 256, 256>>>(out);
}